// round 6
// baseline (speedup 1.0000x reference)
#include <cuda_runtime.h>
#include <math_constants.h>

#define FH 64
#define FW 64
#define FC 128
#define NB 2
#define NROI 256
#define OH 7
#define OW 7
#define NBIN (OH * OW)          // 49
#define SCALE 0.0625f
#define C4 (FC / 4)             // 32 float4 per pixel

// NHWC scratch: [b][y][x][c], 4 MB (device global, no alloc)
__device__ float g_feat_t[NB * FH * FW * FC];

// ---------------------------------------------------------------------------
// Kernel 1: NCHW -> NHWC. One block per (b, y, channel-half): 256 blocks.
// ---------------------------------------------------------------------------
__global__ __launch_bounds__(256) void transpose_nchw_nhwc(const float* __restrict__ feat) {
    __shared__ float s[64][FW + 1];          // 64 x 65 floats = 16.6 KB
    int blk = blockIdx.x;                    // 0..255
    int choff = (blk & 1) * 64;              // channel half
    int row = blk >> 1;                      // 0..127 : b*64 + y
    int b = row >> 6;
    int y = row & 63;

    const float* src = feat + (((size_t)b * FC + choff) * FH + y) * FW;
    #pragma unroll
    for (int it = 0; it < 16; ++it) {
        int idx = threadIdx.x + it * 256;
        int c = idx >> 6;
        int x = idx & 63;
        s[c][x] = src[(size_t)c * FH * FW + x];   // coalesced reads
    }
    __syncthreads();

    float* dst = g_feat_t + (size_t)row * FW * FC + choff;
    #pragma unroll
    for (int it = 0; it < 16; ++it) {
        int idx = threadIdx.x + it * 256;
        int x = idx >> 6;
        int c = idx & 63;
        dst[(size_t)x * FC + c] = s[c][x];   // coalesced writes, bank-free
    }
}

// ---------------------------------------------------------------------------
// Kernel 2: one block (448 thr = 14 warps) per (roi, ph) stripe: 1792 blocks.
// Warp pair (2*pw, 2*pw+1) handles bin pw, splitting region rows even/odd.
// Lane = float4 channel chunk. X is processed in uniform clamped batches of 4
// (duplicate loads are harmless under max) -> always 4 loads in flight, no
// remainder code. ROI bounds decoded once per block into smem.
// ---------------------------------------------------------------------------
__global__ __launch_bounds__(448, 4) void roipool_kernel(const float* __restrict__ rois,
                                                         float* __restrict__ out) {
    __shared__ float4 s_acc[14][C4];         // 7 KB
    __shared__ int s_wb[OW][2];              // ws, we per pw
    __shared__ int s_geo[4];                 // b, hs, he, empty

    int bx = blockIdx.x;
    int r  = bx / OH;
    int ph = bx - r * OH;
    int tid  = threadIdx.x;
    int wid  = tid >> 5;
    int lane = tid & 31;

    if (tid < OW) {                          // per-column bounds
        int x1 = (int)(rois[r * 5 + 1] * SCALE);
        int x2 = (int)(rois[r * 5 + 3] * SCALE);
        int w = x2 - x1;
        s_wb[tid][0] = x1 + (tid * w) / OW;
        s_wb[tid][1] = x1 + ((tid + 1) * w + OW - 1) / OW;
    } else if (tid < 8) {                    // tid == 7: row bounds + flags
        int b  = (int)rois[r * 5 + 0];
        int x1 = (int)(rois[r * 5 + 1] * SCALE);
        int y1 = (int)(rois[r * 5 + 2] * SCALE);
        int x2 = (int)(rois[r * 5 + 3] * SCALE);
        int y2 = (int)(rois[r * 5 + 4] * SCALE);
        int h = y2 - y1;
        int w = x2 - x1;
        s_geo[0] = b;
        s_geo[1] = y1 + (ph * h) / OH;
        s_geo[2] = y1 + ((ph + 1) * h + OH - 1) / OH;
        s_geo[3] = (h <= 0 || w <= 0);
    }
    __syncthreads();

    int b  = s_geo[0];
    int hs = s_geo[1];
    int he = s_geo[2];
    int empty = s_geo[3];

    {
        int pw  = wid >> 1;
        int par = wid & 1;
        int ws = s_wb[pw][0];
        int we = s_wb[pw][1];
        int xe = we - 1;

        float4 acc = make_float4(-CUDART_INF_F, -CUDART_INF_F,
                                 -CUDART_INF_F, -CUDART_INF_F);

        const float4* bbase = reinterpret_cast<const float4*>(g_feat_t)
                            + ((size_t)b * FH * FW) * C4 + lane;

        for (int y = hs + par; y < he; y += 2) {
            const float4* rowp = bbase + (size_t)(y * FW) * C4;
            for (int x = ws; x < we; x += 4) {
                // uniform 4-wide batch; clamped dups are no-ops under max
                float4 v0 = rowp[(size_t)x * C4];
                float4 v1 = rowp[(size_t)min(x + 1, xe) * C4];
                float4 v2 = rowp[(size_t)min(x + 2, xe) * C4];
                float4 v3 = rowp[(size_t)min(x + 3, xe) * C4];
                float4 m01, m23;
                m01.x = fmaxf(v0.x, v1.x); m01.y = fmaxf(v0.y, v1.y);
                m01.z = fmaxf(v0.z, v1.z); m01.w = fmaxf(v0.w, v1.w);
                m23.x = fmaxf(v2.x, v3.x); m23.y = fmaxf(v2.y, v3.y);
                m23.z = fmaxf(v2.z, v3.z); m23.w = fmaxf(v2.w, v3.w);
                acc.x = fmaxf(acc.x, fmaxf(m01.x, m23.x));
                acc.y = fmaxf(acc.y, fmaxf(m01.y, m23.y));
                acc.z = fmaxf(acc.z, fmaxf(m01.z, m23.z));
                acc.w = fmaxf(acc.w, fmaxf(m01.w, m23.w));
            }
        }
        s_acc[wid][lane] = acc;              // STS.128, no conflicts
    }
    __syncthreads();

    // Epilogue: 896 outputs for this (r, ph) slice: out[r][c][ph][pw]
    const float* sf = reinterpret_cast<const float*>(s_acc);  // [14][128]
    float* obase = out + (size_t)r * FC * NBIN + ph * OW;
    #pragma unroll
    for (int it = 0; it < 2; ++it) {
        int t = tid + it * 448;
        int c  = t / OW;
        int pw = t - c * OW;
        float v = fmaxf(sf[(2 * pw) * FC + c], sf[(2 * pw + 1) * FC + c]);
        obase[c * NBIN + pw] = empty ? 0.f : v;
    }
}

extern "C" void kernel_launch(void* const* d_in, const int* in_sizes, int n_in,
                              void* d_out, int out_size) {
    const float* feat = (const float*)d_in[0];   // (2,128,64,64) fp32
    const float* rois = (const float*)d_in[1];   // (256,5) fp32
    float* out = (float*)d_out;                  // (256,128,7,7) fp32

    transpose_nchw_nhwc<<<NB * FH * 2, 256>>>(feat);
    roipool_kernel<<<NROI * OH, 448>>>(rois, out);
}

// round 7
// speedup vs baseline: 1.1109x; 1.1109x over previous
#include <cuda_runtime.h>
#include <math_constants.h>

#define FH 64
#define FW 64
#define FC 128
#define NB 2
#define NROI 256
#define OH 7
#define OW 7
#define NBIN (OH * OW)          // 49
#define SCALE 0.0625f
#define C4 (FC / 4)             // 32 float4 per pixel

// NHWC scratch: [b][y][x][c], 4 MB (device global, no alloc)
__device__ float g_feat_t[NB * FH * FW * FC];

// ---------------------------------------------------------------------------
// Kernel 1: NCHW -> NHWC. One block per (b, y, channel-half): 256 blocks.
// Phase 1: LDG.128 along x. Phase 2: STG.128 along c (4 scalar LDS gather).
// ---------------------------------------------------------------------------
__global__ __launch_bounds__(256) void transpose_nchw_nhwc(const float* __restrict__ feat) {
    __shared__ float s[64][FW + 1];          // 64 x 65 floats = 16.6 KB
    int blk = blockIdx.x;                    // 0..255
    int choff = (blk & 1) * 64;              // channel half
    int row = blk >> 1;                      // 0..127 : b*64 + y
    int b = row >> 6;
    int y = row & 63;

    // Phase 1: float4 loads, coalesced. 64 ch x 16 float4 = 1024 float4.
    const float4* src4 = reinterpret_cast<const float4*>(
        feat + (((size_t)b * FC + choff) * FH + y) * FW);
    const size_t cstr4 = (size_t)FH * FW / 4;          // float4 stride per channel
    #pragma unroll
    for (int it = 0; it < 4; ++it) {
        int idx = threadIdx.x + it * 256;    // 0..1023
        int c  = idx >> 4;                   // 0..63
        int x4 = idx & 15;                   // float4 chunk in x
        float4 v = src4[(size_t)c * cstr4 + x4];
        s[c][x4 * 4 + 0] = v.x;
        s[c][x4 * 4 + 1] = v.y;
        s[c][x4 * 4 + 2] = v.z;
        s[c][x4 * 4 + 3] = v.w;
    }
    __syncthreads();

    // Phase 2: float4 stores along c. dst[x][choff + 4*c4 .. +3]
    float* dst = g_feat_t + (size_t)row * FW * FC + choff;
    #pragma unroll
    for (int it = 0; it < 4; ++it) {
        int idx = threadIdx.x + it * 256;    // 0..1023
        int c4 = idx & 15;                   // 16 float4-chunks of 64 channels
        int x  = idx >> 4;                   // 0..63
        float4 v;
        v.x = s[c4 * 4 + 0][x];
        v.y = s[c4 * 4 + 1][x];
        v.z = s[c4 * 4 + 2][x];
        v.w = s[c4 * 4 + 3][x];
        reinterpret_cast<float4*>(dst + (size_t)x * FC)[c4] = v;   // STG.128
    }
}

// ---------------------------------------------------------------------------
// Kernel 2: one block (448 thr = 14 warps) per (roi, ph) stripe: 1792 blocks.
// Warp pair (2*pw, 2*pw+1) handles bin pw, splitting region rows even/odd.
// Lane = float4 channel chunk -> each region pixel is one coalesced 512B
// warp load. Dynamic-trip x loop (R5 winner) — no duplicate loads.
// ROI bounds decoded once per block into smem; regs capped for 4 blocks/SM.
// ---------------------------------------------------------------------------
__global__ __launch_bounds__(448, 4) void roipool_kernel(const float* __restrict__ rois,
                                                         float* __restrict__ out) {
    __shared__ float4 s_acc[14][C4];         // 7 KB
    __shared__ int s_wb[OW][2];              // ws, we per pw
    __shared__ int s_geo[4];                 // b, hs, he, empty

    int bx = blockIdx.x;
    int r  = bx / OH;
    int ph = bx - r * OH;
    int tid  = threadIdx.x;
    int wid  = tid >> 5;
    int lane = tid & 31;

    if (tid < OW) {                          // per-column bounds
        int x1 = (int)(rois[r * 5 + 1] * SCALE);
        int x2 = (int)(rois[r * 5 + 3] * SCALE);
        int w = x2 - x1;
        s_wb[tid][0] = x1 + (tid * w) / OW;
        s_wb[tid][1] = x1 + ((tid + 1) * w + OW - 1) / OW;
    } else if (tid < 8) {                    // tid == 7: row bounds + flags
        int b  = (int)rois[r * 5 + 0];
        int x1 = (int)(rois[r * 5 + 1] * SCALE);
        int y1 = (int)(rois[r * 5 + 2] * SCALE);
        int x2 = (int)(rois[r * 5 + 3] * SCALE);
        int y2 = (int)(rois[r * 5 + 4] * SCALE);
        int h = y2 - y1;
        int w = x2 - x1;
        s_geo[0] = b;
        s_geo[1] = y1 + (ph * h) / OH;
        s_geo[2] = y1 + ((ph + 1) * h + OH - 1) / OH;
        s_geo[3] = (h <= 0 || w <= 0);
    }
    __syncthreads();

    int b  = s_geo[0];
    int hs = s_geo[1];
    int he = s_geo[2];
    int empty = s_geo[3];

    {
        int pw  = wid >> 1;
        int par = wid & 1;
        int ws = s_wb[pw][0];
        int we = s_wb[pw][1];

        float4 acc = make_float4(-CUDART_INF_F, -CUDART_INF_F,
                                 -CUDART_INF_F, -CUDART_INF_F);

        const float4* bbase = reinterpret_cast<const float4*>(g_feat_t)
                            + ((size_t)b * FH * FW) * C4 + lane;

        for (int y = hs + par; y < he; y += 2) {
            const float4* rowp = bbase + (size_t)(y * FW) * C4;
            #pragma unroll 4
            for (int x = ws; x < we; ++x) {
                float4 v = rowp[(size_t)x * C4];
                acc.x = fmaxf(acc.x, v.x);
                acc.y = fmaxf(acc.y, v.y);
                acc.z = fmaxf(acc.z, v.z);
                acc.w = fmaxf(acc.w, v.w);
            }
        }
        s_acc[wid][lane] = acc;              // STS.128, no conflicts
    }
    __syncthreads();

    // Epilogue: 896 outputs for this (r, ph) slice: out[r][c][ph][pw]
    const float* sf = reinterpret_cast<const float*>(s_acc);  // [14][128]
    float* obase = out + (size_t)r * FC * NBIN + ph * OW;
    #pragma unroll
    for (int it = 0; it < 2; ++it) {
        int t = tid + it * 448;
        int c  = t / OW;
        int pw = t - c * OW;
        float v = fmaxf(sf[(2 * pw) * FC + c], sf[(2 * pw + 1) * FC + c]);
        obase[c * NBIN + pw] = empty ? 0.f : v;
    }
}

extern "C" void kernel_launch(void* const* d_in, const int* in_sizes, int n_in,
                              void* d_out, int out_size) {
    const float* feat = (const float*)d_in[0];   // (2,128,64,64) fp32
    const float* rois = (const float*)d_in[1];   // (256,5) fp32
    float* out = (float*)d_out;                  // (256,128,7,7) fp32

    transpose_nchw_nhwc<<<NB * FH * 2, 256>>>(feat);
    roipool_kernel<<<NROI * OH, 448>>>(rois, out);
}

// round 9
// speedup vs baseline: 1.2495x; 1.1248x over previous
#include <cuda_runtime.h>
#include <math_constants.h>

#define FH 64
#define FW 64
#define FC 128
#define NB 2
#define NROI 256
#define OH 7
#define OW 7
#define NBIN (OH * OW)          // 49
#define SCALE 0.0625f
#define C4 (FC / 4)             // 32 float4 per pixel
#define LVL (NB * FH * FW * FC) // floats per pyramid level (4 MB)

// x-max pyramid, NHWC layout per level: level k = max over columns [x, x+2^k)
// k = 0..3. 16 MB device-global scratch (static, no alloc).
__device__ float g_pyr[4][LVL];

// ---------------------------------------------------------------------------
// Kernel 1: NCHW -> NHWC transpose + x-max pyramid build.
// One block per (b, y, channel-half): 256 blocks. Row tile lives in smem;
// levels built by ping-pong smem max, each stored with coalesced STG.128.
// ---------------------------------------------------------------------------
__global__ __launch_bounds__(256) void transpose_build(const float* __restrict__ feat) {
    __shared__ float sA[64][FW + 1];         // 16.6 KB
    __shared__ float sB[64][FW + 1];         // 16.6 KB
    int blk = blockIdx.x;                    // 0..255
    int choff = (blk & 1) * 64;              // channel half
    int row = blk >> 1;                      // b*64 + y
    int b = row >> 6;
    int y = row & 63;
    int tid = threadIdx.x;

    // Phase 1: coalesced float4 loads of 64 channels x 64 px
    const float4* src4 = reinterpret_cast<const float4*>(
        feat + (((size_t)b * FC + choff) * FH + y) * FW);
    const size_t cstr4 = (size_t)FH * FW / 4;
    #pragma unroll
    for (int it = 0; it < 4; ++it) {
        int idx = tid + it * 256;
        int c  = idx >> 4;
        int x4 = idx & 15;
        float4 v = src4[(size_t)c * cstr4 + x4];
        sA[c][x4 * 4 + 0] = v.x;
        sA[c][x4 * 4 + 1] = v.y;
        sA[c][x4 * 4 + 2] = v.z;
        sA[c][x4 * 4 + 3] = v.w;
    }
    __syncthreads();

    size_t dbase = (size_t)row * FW * FC + choff;

    // store helper (macro keeps NCU lines distinct per level)
#define STORE_LEVEL(buf, k)                                                 \
    {                                                                       \
        float* dst = g_pyr[k] + dbase;                                      \
        _Pragma("unroll")                                                   \
        for (int it = 0; it < 4; ++it) {                                    \
            int idx = tid + it * 256;                                       \
            int c4 = idx & 15;                                              \
            int x  = idx >> 4;                                              \
            float4 v;                                                       \
            v.x = buf[c4 * 4 + 0][x];                                       \
            v.y = buf[c4 * 4 + 1][x];                                       \
            v.z = buf[c4 * 4 + 2][x];                                       \
            v.w = buf[c4 * 4 + 3][x];                                       \
            reinterpret_cast<float4*>(dst + (size_t)x * FC)[c4] = v;        \
        }                                                                   \
    }

#define BUILD_LEVEL(dstbuf, srcbuf, step)                                   \
    {                                                                       \
        _Pragma("unroll")                                                   \
        for (int it = 0; it < 16; ++it) {                                   \
            int idx = tid + it * 256;                                       \
            int c = idx >> 6;                                               \
            int x = idx & 63;                                               \
            int x2 = min(x + (step), 63);                                   \
            dstbuf[c][x] = fmaxf(srcbuf[c][x], srcbuf[c][x2]);              \
        }                                                                   \
    }

    STORE_LEVEL(sA, 0)
    BUILD_LEVEL(sB, sA, 1)                   // level 1 (width 2)
    __syncthreads();
    STORE_LEVEL(sB, 1)
    BUILD_LEVEL(sA, sB, 2)                   // level 2 (width 4)
    __syncthreads();
    STORE_LEVEL(sA, 2)
    BUILD_LEVEL(sB, sA, 4)                   // level 3 (width 8)
    __syncthreads();
    STORE_LEVEL(sB, 3)
#undef STORE_LEVEL
#undef BUILD_LEVEL
}

// ---------------------------------------------------------------------------
// Kernel 2: one block (224 thr = 7 warps) per (roi, ph) stripe: 1792 blocks.
// Warp = bin column pw. Bin row-segment answered by 2 pyramid lookups
// (sparse-table RMQ): lane = channel chunk, 2 independent LDG.128 per row,
// <=10 rows. Results staged in smem, slice written out.
// ---------------------------------------------------------------------------
__global__ __launch_bounds__(224, 8) void roipool_kernel(const float* __restrict__ rois,
                                                         float* __restrict__ out) {
    __shared__ float s_acc[OW][FC];          // 3.5 KB
    __shared__ int s_q[OW][3];               // k, xs0, xs1 per pw
    __shared__ int s_geo[4];                 // b, hs, he, empty

    int bx = blockIdx.x;
    int r  = bx / OH;
    int ph = bx - r * OH;
    int tid  = threadIdx.x;
    int wid  = tid >> 5;                     // == pw (7 warps)
    int lane = tid & 31;

    if (tid < OW) {
        int x1 = (int)(rois[r * 5 + 1] * SCALE);
        int x2 = (int)(rois[r * 5 + 3] * SCALE);
        int w = x2 - x1;
        int ws = x1 + (tid * w) / OW;
        int we = x1 + ((tid + 1) * w + OW - 1) / OW;
        int wp = we - ws;
        int k  = (wp > 0) ? (31 - __clz(wp)) : 0;   // wp <= 10 -> k <= 3
        s_q[tid][0] = k;
        s_q[tid][1] = ws;
        s_q[tid][2] = (wp > 0) ? (we - (1 << k)) : ws;
    } else if (tid < 8) {                    // tid == 7
        int b  = (int)rois[r * 5 + 0];
        int x1 = (int)(rois[r * 5 + 1] * SCALE);
        int y1 = (int)(rois[r * 5 + 2] * SCALE);
        int x2 = (int)(rois[r * 5 + 3] * SCALE);
        int y2 = (int)(rois[r * 5 + 4] * SCALE);
        int h = y2 - y1;
        int w = x2 - x1;
        s_geo[0] = b;
        s_geo[1] = y1 + (ph * h) / OH;
        s_geo[2] = y1 + ((ph + 1) * h + OH - 1) / OH;
        s_geo[3] = (h <= 0 || w <= 0);
    }
    __syncthreads();

    int b  = s_geo[0];
    int hs = s_geo[1];
    int he = s_geo[2];
    int empty = s_geo[3];

    {
        int k   = s_q[wid][0];
        int xs0 = s_q[wid][1];
        int xs1 = s_q[wid][2];

        float4 acc = make_float4(-CUDART_INF_F, -CUDART_INF_F,
                                 -CUDART_INF_F, -CUDART_INF_F);

        const float4* base = reinterpret_cast<const float4*>(g_pyr[k])
                           + ((size_t)b * FH * FW) * C4 + lane;
        const float4* p0 = base + (size_t)xs0 * C4;
        const float4* p1 = base + (size_t)xs1 * C4;

        #pragma unroll 2
        for (int y = hs; y < he; ++y) {
            size_t ro = (size_t)(y * FW) * C4;
            float4 v0 = p0[ro];              // 2 independent loads per row
            float4 v1 = p1[ro];
            acc.x = fmaxf(acc.x, fmaxf(v0.x, v1.x));
            acc.y = fmaxf(acc.y, fmaxf(v0.y, v1.y));
            acc.z = fmaxf(acc.z, fmaxf(v0.z, v1.z));
            acc.w = fmaxf(acc.w, fmaxf(v0.w, v1.w));
        }
        reinterpret_cast<float4*>(s_acc[wid])[lane] = acc;
    }
    __syncthreads();

    // Epilogue: 896 outputs for this (r, ph) slice: out[r][c][ph][pw]
    float* obase = out + (size_t)r * FC * NBIN + ph * OW;
    #pragma unroll
    for (int it = 0; it < 4; ++it) {
        int t = tid + it * 224;
        int c  = t / OW;
        int pw = t - c * OW;
        obase[c * NBIN + pw] = empty ? 0.f : s_acc[pw][c];
    }
}

extern "C" void kernel_launch(void* const* d_in, const int* in_sizes, int n_in,
                              void* d_out, int out_size) {
    const float* feat = (const float*)d_in[0];   // (2,128,64,64) fp32
    const float* rois = (const float*)d_in[1];   // (256,5) fp32
    float* out = (float*)d_out;                  // (256,128,7,7) fp32

    transpose_build<<<NB * FH * 2, 256>>>(feat);
    roipool_kernel<<<NROI * OH, 224>>>(rois, out);
}